// round 15
// baseline (speedup 1.0000x reference)
#include <cuda_runtime.h>
#include <cuda_bf16.h>
#include <cstdint>

// Problem constants
#define Nn   128
#define Cc   1024
#define HW   196
#define Hh   14
#define Oo   256
#define KTOP 16

// Output offsets (float32 elements)
#define OFF_MAX  0
#define OFF_MED  524288
#define OFF_ROWS 1048576
#define OFF_COLS 1052672

// GEMM: logical K = 3072 (segments: A-hi*B-hi, A-hi*B-lo, A-lo*B-hi)
// split-K = 4 -> 768 per split = 6 chunks of 128
#define NCH 6

// Scratch
__device__ float g_part[4 * Nn * HW];
__device__ int   g_scene[Nn * 32];
__device__ __nv_bfloat16 g_Abf[2][2048 * 2048];  // [g][m][c]: [0,1024)=hi, [1024,2048)=lo
__device__ __nv_bfloat16 g_Bbf[2][256 * 2048];   // [g][o][c]: hi | lo
__device__ float g_pacc[4 * 2 * 2048 * 256];     // [split][g][m][o] fp32 partials

// ---------------------------------------------------------------------------
__device__ __forceinline__ uint32_t smem_u32(const void* p) {
    uint32_t a;
    asm("{ .reg .u64 t; cvta.to.shared.u64 t, %1; cvt.u32.u64 %0, t; }" : "=r"(a) : "l"(p));
    return a;
}

#define CP_ASYNC16(dst, src) \
    asm volatile("cp.async.cg.shared.global [%0], [%1], 16;" :: "r"(dst), "l"(src) : "memory")
#define CP_COMMIT() asm volatile("cp.async.commit_group;" ::: "memory")
#define CP_WAIT(n)  asm volatile("cp.async.wait_group %0;" :: "n"(n) : "memory")

#define LDSM_X4(r, addr)                                                     \
    asm volatile("ldmatrix.sync.aligned.m8n8.x4.shared.b16 {%0,%1,%2,%3}, [%4];" \
        : "=r"((r)[0]), "=r"((r)[1]), "=r"((r)[2]), "=r"((r)[3]) : "r"(addr))

#define MMA_BF16(d, a, b0, b1)                                               \
    asm volatile("mma.sync.aligned.m16n8k16.row.col.f32.bf16.bf16.f32 "      \
        "{%0,%1,%2,%3},{%4,%5,%6,%7},{%8,%9},{%0,%1,%2,%3};"                 \
        : "+f"((d)[0]), "+f"((d)[1]), "+f"((d)[2]), "+f"((d)[3])             \
        : "r"((a)[0]), "r"((a)[1]), "r"((a)[2]), "r"((a)[3]),                \
          "r"(b0), "r"(b1))

__device__ __forceinline__ uint32_t pack2(float v0, float v1, float& r0, float& r1) {
    __nv_bfloat16 h0 = __float2bfloat16(v0);
    __nv_bfloat16 h1 = __float2bfloat16(v1);
    r0 = v0 - __bfloat162float(h0);
    r1 = v1 - __bfloat162float(h1);
    return (uint32_t)__bfloat16_as_ushort(h0) |
           ((uint32_t)__bfloat16_as_ushort(h1) << 16);
}

// ---------------------------------------------------------------------------
// 1) Channel sum stage 1 (verified order/config) + embedded weight prep.
//    grid (4 chunks, 128 n), 224 threads.
__global__ void k_sum_prepw(const float* __restrict__ x,
                            const float* __restrict__ wmax,
                            const float* __restrict__ wmed) {
    int n = blockIdx.y, tid = threadIdx.x;
    if (tid < HW) {
        const float* base = x + (n * Cc + blockIdx.x * 256) * HW + tid;
        float acc = 0.f;
#pragma unroll 8
        for (int c = 0; c < 256; c++) acc += base[c * HW];
        g_part[(blockIdx.x * Nn + n) * HW + tid] = acc;
    }
    // Embedded prepw: 65536 jobs of 4 channel-pairs each
    int idx = (blockIdx.y * 4 + blockIdx.x) * 224 + tid;
    if (idx < 65536) {
        int cq = idx & 127, o = (idx >> 7) & 255, g = idx >> 15;
        const float* W = g ? wmed : wmax;
        const float4* wr = (const float4*)(W + o * 1024 + cq * 8);
        float4 v0 = wr[0], v1 = wr[1];
        uint32_t hi[4], lo[4];
        float r0, r1, d0, d1;
        hi[0] = pack2(v0.x, v0.y, r0, r1); lo[0] = pack2(r0, r1, d0, d1);
        hi[1] = pack2(v0.z, v0.w, r0, r1); lo[1] = pack2(r0, r1, d0, d1);
        hi[2] = pack2(v1.x, v1.y, r0, r1); lo[2] = pack2(r0, r1, d0, d1);
        hi[3] = pack2(v1.z, v1.w, r0, r1); lo[3] = pack2(r0, r1, d0, d1);
        uint4* rhi = (uint4*)(g_Bbf[g] + o * 2048);
        uint4* rlo = (uint4*)(g_Bbf[g] + o * 2048 + 1024);
        rhi[cq] = make_uint4(hi[0], hi[1], hi[2], hi[3]);
        rlo[cq] = make_uint4(lo[0], lo[1], lo[2], lo[3]);
    }
}

// ---------------------------------------------------------------------------
// 2+3) Fused combine + rank-sort + gather + split-bf16.
//    grid (32 c-chunks of 32ch, 128 n), 256 thr.
//    Each block recomputes the rank locally (bitwise-identical combine order);
//    block c0==0 additionally writes g_scene / rows / cols.
__global__ void k_gather(const float* __restrict__ x, float* __restrict__ out) {
    __shared__ float s[32 * HW];
    __shared__ float fre[HW];
    __shared__ int sc[32];
    int n = blockIdx.y, c0 = blockIdx.x * 32, tid = threadIdx.x;

    // fre combine (order-preserving) — issued first
    if (tid < HW) {
        int i = n * HW + tid;
        const int NH = Nn * HW;
        fre[tid] = (g_part[i] + g_part[NH + i]) +
                   (g_part[2 * NH + i] + g_part[3 * NH + i]);
    }
    // Staging loads of this block's 32-channel slab (independent of sort)
    const float4* src = (const float4*)(x + (n * Cc + c0) * HW);
    float4* s4 = (float4*)s;
#pragma unroll
    for (int i = 0; i < 7; i++) {
        int j = tid + i * 256;
        if (j < 32 * HW / 4) s4[j] = src[j];
    }
    __syncthreads();

    // Stable descending rank; scatter scene slots into smem
    if (tid < HW) {
        float v = fre[tid];
        int r = 0;
#pragma unroll 4
        for (int j = 0; j < HW; j++) {
            float u = fre[j];
            r += (u > v) || (u == v && j < tid);
        }
        int slot = -1;
        if (r < KTOP) slot = r;
        else if (r >= 89 && r < 89 + KTOP) slot = KTOP + (r - 89);
        if (slot >= 0) {
            sc[slot] = tid;
            if (c0 == 0) {
                g_scene[n * 32 + slot] = tid;
                out[OFF_ROWS + n * 32 + slot] = (float)(tid / Hh);
                out[OFF_COLS + n * 32 + slot] = (float)(tid % Hh);
            }
        }
    }
    __syncthreads();

    // Gather + split-bf16 emit
    int k = tid >> 3, cp0 = tid & 7;
    int p = sc[k], g = k >> 4;
    int row = n * 16 + (k & 15);
    uint32_t* Ahi = (uint32_t*)(g_Abf[g] + row * 2048 + c0);
    uint32_t* Alo = (uint32_t*)(g_Abf[g] + row * 2048 + 1024 + c0);
#pragma unroll
    for (int t = 0; t < 2; t++) {
        int cp = cp0 + t * 8;
        int cl = cp * 2;
        float v0 = s[cl * HW + p], v1 = s[(cl + 1) * HW + p];
        float r0, r1, d0, d1;
        uint32_t hi = pack2(v0, v1, r0, r1);
        uint32_t lo = pack2(r0, r1, d0, d1);
        Ahi[cp] = hi;
        Alo[cp] = lo;
    }
}

// ---------------------------------------------------------------------------
// 4) mma.sync bf16 GEMM (round-13 version). Block tile 128(M) x 256(N),
//    warp tile 64x64, K-chunk 128, split-K=4, 2-stage cp.async.
//    grid (4 splits, 16 mtiles, 2 graphs), 256 thr (8 warps, 2m x 4n).
#define ROWB 272       // 128 bf16 + 16B pad: conflict-free ldmatrix
#define STG  104448    // (128 + 256) * 272
#define SMEM_GEMM 208896

__global__ __launch_bounds__(256, 1) void k_gemm() {
    extern __shared__ char smem[];
    uint32_t sb = smem_u32(smem);
    int tid = threadIdx.x, lane = tid & 31, w = tid >> 5;
    int split = blockIdx.x, g = blockIdx.z, m0 = blockIdx.y * 128;
    const __nv_bfloat16* Ab = g_Abf[g];
    const __nv_bfloat16* Bb = g_Bbf[g];

    int ar = tid >> 4, ach = tid & 15;   // 16 rows x 16 16B-chunks per pass

    auto issue = [&](int it) {
        int st = it & 1;
        int k0 = split * 768 + it * 128, seg = k0 >> 10, kk = k0 & 1023;
        int acol = (seg == 2) ? (1024 + kk) : kk;   // segs: hi, hi, lo
        int bcol = (seg == 1) ? (1024 + kk) : kk;   // segs: hi, lo, hi
        uint32_t sA = sb + st * STG, sB = sA + 34816;
#pragma unroll
        for (int i = 0; i < 8; i++) {
            int r = ar + i * 16;
            CP_ASYNC16(sA + r * ROWB + ach * 16,
                       (const void*)(Ab + (m0 + r) * 2048 + acol + ach * 8));
        }
#pragma unroll
        for (int i = 0; i < 16; i++) {
            int r = ar + i * 16;
            CP_ASYNC16(sB + r * ROWB + ach * 16,
                       (const void*)(Bb + r * 2048 + bcol + ach * 8));
        }
        CP_COMMIT();
    };

    int wm = (w >> 2) * 64, wn = (w & 3) * 64;
    float acc[4][8][4] = {};

    issue(0);
    issue(1);
    for (int it = 0; it < NCH; it++) {
        int st = it & 1;
        if (it == NCH - 1) { CP_WAIT(0); } else { CP_WAIT(1); }
        __syncthreads();
        uint32_t abase = sb + st * STG;
        uint32_t bbase = abase + 34816;
#pragma unroll
        for (int ks = 0; ks < 8; ks++) {
            int kb = ks * 16 * 2;   // byte offset of this k16 step
            uint32_t a[4][4], b[4][4];
#pragma unroll
            for (int mi = 0; mi < 4; mi++)
                LDSM_X4(a[mi], abase + (wm + mi * 16 + (lane & 15)) * ROWB +
                               kb + (lane >> 4) * 16);
#pragma unroll
            for (int nj = 0; nj < 4; nj++)
                LDSM_X4(b[nj], bbase +
                        (wn + nj * 16 + (lane & 7) + ((lane >> 4) & 1) * 8) * ROWB +
                        kb + ((lane >> 3) & 1) * 16);
#pragma unroll
            for (int mi = 0; mi < 4; mi++)
#pragma unroll
                for (int ni = 0; ni < 8; ni++)
                    MMA_BF16(acc[mi][ni], a[mi],
                             b[ni >> 1][(ni & 1) * 2], b[ni >> 1][(ni & 1) * 2 + 1]);
        }
        __syncthreads();
        if (it + 2 < NCH) issue(it + 2);
    }

    // Epilogue: raw fp32 partials to g_pacc[split][g][m][o]
    int t4r = lane >> 2, t4c = (lane & 3) * 2;
    float* P = g_pacc + ((size_t)(split * 2 + g) * 2048) * 256;
#pragma unroll
    for (int mi = 0; mi < 4; mi++) {
#pragma unroll
        for (int ni = 0; ni < 8; ni++) {
            int row = m0 + wm + mi * 16 + t4r;
            int col = wn + ni * 8 + t4c;
            *(float2*)&P[row * 256 + col] =
                make_float2(acc[mi][ni][0], acc[mi][ni][1]);
            *(float2*)&P[(row + 8) * 256 + col] =
                make_float2(acc[mi][ni][2], acc[mi][ni][3]);
        }
    }
}

// ---------------------------------------------------------------------------
// 5) Split-K sum + BN + ReLU + normalized adjacency matmul. grid 128, 256 thr
__global__ void k_final(
    float* __restrict__ out,
    const float* __restrict__ gmax, const float* __restrict__ bmax,
    const float* __restrict__ mmax, const float* __restrict__ vmax,
    const float* __restrict__ gmed, const float* __restrict__ bmed,
    const float* __restrict__ mmed, const float* __restrict__ vmed) {
    __shared__ float sr[32], scc[32], L[2][16][16], dinv[32];
    int n = blockIdx.x, tid = threadIdx.x;
    if (tid < 32) {
        int p = g_scene[n * 32 + tid];
        sr[tid]  = (float)(p / Hh);
        scc[tid] = (float)(p % Hh);
    }
    __syncthreads();
    for (int e = tid; e < 512; e += 256) {
        int g = e >> 8, i = (e >> 4) & 15, j = e & 15, b = g * 16;
        float dr = sr[b + i] - sr[b + j];
        float dc = scc[b + i] - scc[b + j];
        L[g][i][j] = 1.f / (1.f + sqrtf(dr * dr + dc * dc));
    }
    __syncthreads();
    if (tid < 32) {
        int g = tid >> 4, i = tid & 15;
        float s = 0.f;
#pragma unroll
        for (int j = 0; j < 16; j++) s += L[g][i][j];
        dinv[tid] = rsqrtf(s);
    }
    __syncthreads();
    for (int e = tid; e < 512; e += 256) {
        int g = e >> 8, i = (e >> 4) & 15, j = e & 15;
        L[g][i][j] *= dinv[g * 16 + i] * dinv[g * 16 + j];
    }
    __syncthreads();
    int o = tid;  // 0..255
#pragma unroll
    for (int g = 0; g < 2; g++) {
        const float* gm = g ? gmed : gmax;
        const float* bt = g ? bmed : bmax;
        const float* mn = g ? mmed : mmax;
        const float* vr = g ? vmed : vmax;
        float scale = gm[o] * rsqrtf(vr[o] + 1e-5f);
        float bias  = bt[o] - mn[o] * scale;
        float xv[16];
#pragma unroll
        for (int j = 0; j < 16; j++) {
            size_t m = (size_t)(n * 16 + j);
            float s = (g_pacc[((0 * 2 + g) * 2048 + m) * 256 + o] +
                       g_pacc[((1 * 2 + g) * 2048 + m) * 256 + o]) +
                      (g_pacc[((2 * 2 + g) * 2048 + m) * 256 + o] +
                       g_pacc[((3 * 2 + g) * 2048 + m) * 256 + o]);
            xv[j] = fmaxf(fmaf(s, scale, bias), 0.f);
        }
        float* O = out + (g ? OFF_MED : OFF_MAX) + n * 4096 + o;
#pragma unroll
        for (int i = 0; i < 16; i++) {
            float acc = 0.f;
#pragma unroll
            for (int j = 0; j < 16; j++) acc = fmaf(L[g][i][j], xv[j], acc);
            O[i * Oo] = acc;
        }
    }
}

// ---------------------------------------------------------------------------
extern "C" void kernel_launch(void* const* d_in, const int* in_sizes, int n_in,
                              void* d_out, int out_size) {
    const float* x     = (const float*)d_in[0];
    const float* w_max = (const float*)d_in[2];
    const float* gmax  = (const float*)d_in[3];
    const float* bmax  = (const float*)d_in[4];
    const float* mmax  = (const float*)d_in[5];
    const float* vmax  = (const float*)d_in[6];
    const float* w_med = (const float*)d_in[7];
    const float* gmed  = (const float*)d_in[8];
    const float* bmed  = (const float*)d_in[9];
    const float* mmed  = (const float*)d_in[10];
    const float* vmed  = (const float*)d_in[11];
    float* out = (float*)d_out;

    cudaFuncSetAttribute(k_gemm, cudaFuncAttributeMaxDynamicSharedMemorySize,
                         SMEM_GEMM);

    k_sum_prepw<<<dim3(4, 128), 224>>>(x, w_max, w_med);
    k_gather<<<dim3(32, 128), 256>>>(x, out);
    k_gemm<<<dim3(4, 16, 2), 256, SMEM_GEMM>>>();
    k_final<<<128, 256>>>(out, gmax, bmax, mmax, vmax,
                          gmed, bmed, mmed, vmed);
}

// round 16
// speedup vs baseline: 1.2422x; 1.2422x over previous
#include <cuda_runtime.h>
#include <cuda_bf16.h>
#include <cstdint>

// Problem constants
#define Nn   128
#define Cc   1024
#define HW   196
#define Hh   14
#define Oo   256
#define KTOP 16

// Output offsets (float32 elements)
#define OFF_MAX  0
#define OFF_MED  524288
#define OFF_ROWS 1048576
#define OFF_COLS 1052672

// GEMM: logical K = 3072 (segments: A-hi*B-hi, A-hi*B-lo, A-lo*B-hi)
// split-K = 4 -> 768 per split = 6 chunks of 128
#define NCH 6

// Scratch
__device__ float g_part[4 * Nn * HW];
__device__ int   g_scene[Nn * 32];
__device__ __nv_bfloat16 g_Abf[2][2048 * 2048];  // [g][m][c]: [0,1024)=hi, [1024,2048)=lo
__device__ __nv_bfloat16 g_Bbf[2][256 * 2048];   // [g][o][c]: hi | lo
__device__ float g_pacc[4 * 2 * 2048 * 256];     // [split][g][m][o] fp32 partials

// ---------------------------------------------------------------------------
__device__ __forceinline__ uint32_t smem_u32(const void* p) {
    uint32_t a;
    asm("{ .reg .u64 t; cvta.to.shared.u64 t, %1; cvt.u32.u64 %0, t; }" : "=r"(a) : "l"(p));
    return a;
}

#define CP_ASYNC16(dst, src) \
    asm volatile("cp.async.cg.shared.global [%0], [%1], 16;" :: "r"(dst), "l"(src) : "memory")
#define CP_COMMIT() asm volatile("cp.async.commit_group;" ::: "memory")
#define CP_WAIT(n)  asm volatile("cp.async.wait_group %0;" :: "n"(n) : "memory")

#define LDSM_X4(r, addr)                                                     \
    asm volatile("ldmatrix.sync.aligned.m8n8.x4.shared.b16 {%0,%1,%2,%3}, [%4];" \
        : "=r"((r)[0]), "=r"((r)[1]), "=r"((r)[2]), "=r"((r)[3]) : "r"(addr))

#define MMA_BF16(d, a, b0, b1)                                               \
    asm volatile("mma.sync.aligned.m16n8k16.row.col.f32.bf16.bf16.f32 "      \
        "{%0,%1,%2,%3},{%4,%5,%6,%7},{%8,%9},{%0,%1,%2,%3};"                 \
        : "+f"((d)[0]), "+f"((d)[1]), "+f"((d)[2]), "+f"((d)[3])             \
        : "r"((a)[0]), "r"((a)[1]), "r"((a)[2]), "r"((a)[3]),                \
          "r"(b0), "r"(b1))

__device__ __forceinline__ uint32_t pack2(float v0, float v1, float& r0, float& r1) {
    __nv_bfloat16 h0 = __float2bfloat16(v0);
    __nv_bfloat16 h1 = __float2bfloat16(v1);
    r0 = v0 - __bfloat162float(h0);
    r1 = v1 - __bfloat162float(h1);
    return (uint32_t)__bfloat16_as_ushort(h0) |
           ((uint32_t)__bfloat16_as_ushort(h1) << 16);
}

// ---------------------------------------------------------------------------
// 1) Channel sum stage 1 (verified order/config) + embedded weight prep.
//    grid (4 chunks, 128 n), 224 threads.
__global__ void k_sum_prepw(const float* __restrict__ x,
                            const float* __restrict__ wmax,
                            const float* __restrict__ wmed) {
    int n = blockIdx.y, tid = threadIdx.x;
    if (tid < HW) {
        const float* base = x + (n * Cc + blockIdx.x * 256) * HW + tid;
        float acc = 0.f;
#pragma unroll 8
        for (int c = 0; c < 256; c++) acc += base[c * HW];
        g_part[(blockIdx.x * Nn + n) * HW + tid] = acc;
    }
    // Embedded prepw: 65536 jobs of 4 channel-pairs each
    int idx = (blockIdx.y * 4 + blockIdx.x) * 224 + tid;
    if (idx < 65536) {
        int cq = idx & 127, o = (idx >> 7) & 255, g = idx >> 15;
        const float* W = g ? wmed : wmax;
        const float4* wr = (const float4*)(W + o * 1024 + cq * 8);
        float4 v0 = wr[0], v1 = wr[1];
        uint32_t hi[4], lo[4];
        float r0, r1, d0, d1;
        hi[0] = pack2(v0.x, v0.y, r0, r1); lo[0] = pack2(r0, r1, d0, d1);
        hi[1] = pack2(v0.z, v0.w, r0, r1); lo[1] = pack2(r0, r1, d0, d1);
        hi[2] = pack2(v1.x, v1.y, r0, r1); lo[2] = pack2(r0, r1, d0, d1);
        hi[3] = pack2(v1.z, v1.w, r0, r1); lo[3] = pack2(r0, r1, d0, d1);
        uint4* rhi = (uint4*)(g_Bbf[g] + o * 2048);
        uint4* rlo = (uint4*)(g_Bbf[g] + o * 2048 + 1024);
        rhi[cq] = make_uint4(hi[0], hi[1], hi[2], hi[3]);
        rlo[cq] = make_uint4(lo[0], lo[1], lo[2], lo[3]);
    }
}

// ---------------------------------------------------------------------------
// 2) Fused chunk-combine + stable descending rank-sort. grid 128, 224 thr.
__global__ void k_sort(float* __restrict__ out) {
    __shared__ float s[HW];
    int n = blockIdx.x, tid = threadIdx.x;
    if (tid < HW) {
        int i = n * HW + tid;
        const int NH = Nn * HW;
        s[tid] = (g_part[i] + g_part[NH + i]) +
                 (g_part[2 * NH + i] + g_part[3 * NH + i]);
    }
    __syncthreads();
    if (tid >= HW) return;
    float v = s[tid];
    int r = 0;
#pragma unroll 4
    for (int j = 0; j < HW; j++) {
        float u = s[j];
        r += (u > v) || (u == v && j < tid);
    }
    int slot = -1;
    if (r < KTOP) slot = r;
    else if (r >= 89 && r < 89 + KTOP) slot = KTOP + (r - 89);
    if (slot >= 0) {
        g_scene[n * 32 + slot] = tid;
        out[OFF_ROWS + n * 32 + slot] = (float)(tid / Hh);
        out[OFF_COLS + n * 32 + slot] = (float)(tid % Hh);
    }
}

// ---------------------------------------------------------------------------
// 3) Gather + split-bf16. grid (32 c-chunks of 32ch, 128 n), 256 thr
__global__ void k_gather(const float* __restrict__ x) {
    __shared__ float s[32 * HW];
    __shared__ int sc[32];
    int n = blockIdx.y, c0 = blockIdx.x * 32, tid = threadIdx.x;
    if (tid < 32) sc[tid] = g_scene[n * 32 + tid];
    const float4* src = (const float4*)(x + (n * Cc + c0) * HW);
    float4* s4 = (float4*)s;
#pragma unroll
    for (int i = 0; i < 7; i++) {
        int j = tid + i * 256;
        if (j < 32 * HW / 4) s4[j] = src[j];
    }
    __syncthreads();
    int k = tid >> 3, cp0 = tid & 7;
    int p = sc[k], g = k >> 4;
    int row = n * 16 + (k & 15);
    uint32_t* Ahi = (uint32_t*)(g_Abf[g] + row * 2048 + c0);
    uint32_t* Alo = (uint32_t*)(g_Abf[g] + row * 2048 + 1024 + c0);
#pragma unroll
    for (int t = 0; t < 2; t++) {
        int cp = cp0 + t * 8;
        int cl = cp * 2;
        float v0 = s[cl * HW + p], v1 = s[(cl + 1) * HW + p];
        float r0, r1, d0, d1;
        uint32_t hi = pack2(v0, v1, r0, r1);
        uint32_t lo = pack2(r0, r1, d0, d1);
        Ahi[cp] = hi;
        Alo[cp] = lo;
    }
}

// ---------------------------------------------------------------------------
// 4) mma.sync bf16 GEMM (round-13 version). Block tile 128(M) x 256(N),
//    warp tile 64x64, K-chunk 128, split-K=4, 2-stage cp.async.
//    grid (4 splits, 16 mtiles, 2 graphs), 256 thr (8 warps, 2m x 4n).
#define ROWB 272       // 128 bf16 + 16B pad: conflict-free ldmatrix
#define STG  104448    // (128 + 256) * 272
#define SMEM_GEMM 208896

__global__ __launch_bounds__(256, 1) void k_gemm() {
    extern __shared__ char smem[];
    uint32_t sb = smem_u32(smem);
    int tid = threadIdx.x, lane = tid & 31, w = tid >> 5;
    int split = blockIdx.x, g = blockIdx.z, m0 = blockIdx.y * 128;
    const __nv_bfloat16* Ab = g_Abf[g];
    const __nv_bfloat16* Bb = g_Bbf[g];

    int ar = tid >> 4, ach = tid & 15;   // 16 rows x 16 16B-chunks per pass

    auto issue = [&](int it) {
        int st = it & 1;
        int k0 = split * 768 + it * 128, seg = k0 >> 10, kk = k0 & 1023;
        int acol = (seg == 2) ? (1024 + kk) : kk;   // segs: hi, hi, lo
        int bcol = (seg == 1) ? (1024 + kk) : kk;   // segs: hi, lo, hi
        uint32_t sA = sb + st * STG, sB = sA + 34816;
#pragma unroll
        for (int i = 0; i < 8; i++) {
            int r = ar + i * 16;
            CP_ASYNC16(sA + r * ROWB + ach * 16,
                       (const void*)(Ab + (m0 + r) * 2048 + acol + ach * 8));
        }
#pragma unroll
        for (int i = 0; i < 16; i++) {
            int r = ar + i * 16;
            CP_ASYNC16(sB + r * ROWB + ach * 16,
                       (const void*)(Bb + r * 2048 + bcol + ach * 8));
        }
        CP_COMMIT();
    };

    int wm = (w >> 2) * 64, wn = (w & 3) * 64;
    float acc[4][8][4] = {};

    issue(0);
    issue(1);
    for (int it = 0; it < NCH; it++) {
        int st = it & 1;
        if (it == NCH - 1) { CP_WAIT(0); } else { CP_WAIT(1); }
        __syncthreads();
        uint32_t abase = sb + st * STG;
        uint32_t bbase = abase + 34816;
#pragma unroll
        for (int ks = 0; ks < 8; ks++) {
            int kb = ks * 16 * 2;   // byte offset of this k16 step
            uint32_t a[4][4], b[4][4];
#pragma unroll
            for (int mi = 0; mi < 4; mi++)
                LDSM_X4(a[mi], abase + (wm + mi * 16 + (lane & 15)) * ROWB +
                               kb + (lane >> 4) * 16);
#pragma unroll
            for (int nj = 0; nj < 4; nj++)
                LDSM_X4(b[nj], bbase +
                        (wn + nj * 16 + (lane & 7) + ((lane >> 4) & 1) * 8) * ROWB +
                        kb + ((lane >> 3) & 1) * 16);
#pragma unroll
            for (int mi = 0; mi < 4; mi++)
#pragma unroll
                for (int ni = 0; ni < 8; ni++)
                    MMA_BF16(acc[mi][ni], a[mi],
                             b[ni >> 1][(ni & 1) * 2], b[ni >> 1][(ni & 1) * 2 + 1]);
        }
        __syncthreads();
        if (it + 2 < NCH) issue(it + 2);
    }

    // Epilogue: raw fp32 partials to g_pacc[split][g][m][o]
    int t4r = lane >> 2, t4c = (lane & 3) * 2;
    float* P = g_pacc + ((size_t)(split * 2 + g) * 2048) * 256;
#pragma unroll
    for (int mi = 0; mi < 4; mi++) {
#pragma unroll
        for (int ni = 0; ni < 8; ni++) {
            int row = m0 + wm + mi * 16 + t4r;
            int col = wn + ni * 8 + t4c;
            *(float2*)&P[row * 256 + col] =
                make_float2(acc[mi][ni][0], acc[mi][ni][1]);
            *(float2*)&P[(row + 8) * 256 + col] =
                make_float2(acc[mi][ni][2], acc[mi][ni][3]);
        }
    }
}

// ---------------------------------------------------------------------------
// 5) Split-K sum + BN + ReLU + normalized adjacency matmul, float4 loads.
//    grid 128, 128 thr: thread = (g = tid>>6, o-quad = (tid&63)*4).
__global__ void k_final(
    float* __restrict__ out,
    const float* __restrict__ gmax, const float* __restrict__ bmax,
    const float* __restrict__ mmax, const float* __restrict__ vmax,
    const float* __restrict__ gmed, const float* __restrict__ bmed,
    const float* __restrict__ mmed, const float* __restrict__ vmed) {
    __shared__ float sr[32], scc[32], L[2][16][16], dinv[32];
    int n = blockIdx.x, tid = threadIdx.x;   // 128 threads
    if (tid < 32) {
        int p = g_scene[n * 32 + tid];
        sr[tid]  = (float)(p / Hh);
        scc[tid] = (float)(p % Hh);
    }
    __syncthreads();
    for (int e = tid; e < 512; e += 128) {
        int g = e >> 8, i = (e >> 4) & 15, j = e & 15, b = g * 16;
        float dr = sr[b + i] - sr[b + j];
        float dc = scc[b + i] - scc[b + j];
        L[g][i][j] = 1.f / (1.f + sqrtf(dr * dr + dc * dc));
    }
    __syncthreads();
    if (tid < 32) {
        int g = tid >> 4, i = tid & 15;
        float s = 0.f;
#pragma unroll
        for (int j = 0; j < 16; j++) s += L[g][i][j];
        dinv[tid] = rsqrtf(s);
    }
    __syncthreads();
    for (int e = tid; e < 512; e += 128) {
        int g = e >> 8, i = (e >> 4) & 15, j = e & 15;
        L[g][i][j] *= dinv[g * 16 + i] * dinv[g * 16 + j];
    }
    __syncthreads();

    int g = tid >> 6, oq = (tid & 63) * 4;
    const float* gm = g ? gmed : gmax;
    const float* bt = g ? bmed : bmax;
    const float* mn = g ? mmed : mmax;
    const float* vr = g ? vmed : vmax;
    float sc4[4], bi4[4];
#pragma unroll
    for (int c = 0; c < 4; c++) {
        float s = gm[oq + c] * rsqrtf(vr[oq + c] + 1e-5f);
        sc4[c] = s;
        bi4[c] = bt[oq + c] - mn[oq + c] * s;
    }

    float4 xv[16];
#pragma unroll
    for (int j = 0; j < 16; j++) {
        size_t m = (size_t)(n * 16 + j);
        float4 p0 = *(const float4*)&g_pacc[((0 * 2 + g) * 2048 + m) * 256 + oq];
        float4 p1 = *(const float4*)&g_pacc[((1 * 2 + g) * 2048 + m) * 256 + oq];
        float4 p2 = *(const float4*)&g_pacc[((2 * 2 + g) * 2048 + m) * 256 + oq];
        float4 p3 = *(const float4*)&g_pacc[((3 * 2 + g) * 2048 + m) * 256 + oq];
        float4 v;
        v.x = fmaxf(fmaf((p0.x + p1.x) + (p2.x + p3.x), sc4[0], bi4[0]), 0.f);
        v.y = fmaxf(fmaf((p0.y + p1.y) + (p2.y + p3.y), sc4[1], bi4[1]), 0.f);
        v.z = fmaxf(fmaf((p0.z + p1.z) + (p2.z + p3.z), sc4[2], bi4[2]), 0.f);
        v.w = fmaxf(fmaf((p0.w + p1.w) + (p2.w + p3.w), sc4[3], bi4[3]), 0.f);
        xv[j] = v;
    }

    float* O = out + (g ? OFF_MED : OFF_MAX) + n * 4096 + oq;
#pragma unroll
    for (int i = 0; i < 16; i++) {
        float4 acc = make_float4(0.f, 0.f, 0.f, 0.f);
#pragma unroll
        for (int j = 0; j < 16; j++) {
            float l = L[g][i][j];
            acc.x = fmaf(l, xv[j].x, acc.x);
            acc.y = fmaf(l, xv[j].y, acc.y);
            acc.z = fmaf(l, xv[j].z, acc.z);
            acc.w = fmaf(l, xv[j].w, acc.w);
        }
        *(float4*)&O[i * Oo] = acc;
    }
}

// ---------------------------------------------------------------------------
extern "C" void kernel_launch(void* const* d_in, const int* in_sizes, int n_in,
                              void* d_out, int out_size) {
    const float* x     = (const float*)d_in[0];
    const float* w_max = (const float*)d_in[2];
    const float* gmax  = (const float*)d_in[3];
    const float* bmax  = (const float*)d_in[4];
    const float* mmax  = (const float*)d_in[5];
    const float* vmax  = (const float*)d_in[6];
    const float* w_med = (const float*)d_in[7];
    const float* gmed  = (const float*)d_in[8];
    const float* bmed  = (const float*)d_in[9];
    const float* mmed  = (const float*)d_in[10];
    const float* vmed  = (const float*)d_in[11];
    float* out = (float*)d_out;

    cudaFuncSetAttribute(k_gemm, cudaFuncAttributeMaxDynamicSharedMemorySize,
                         SMEM_GEMM);

    k_sum_prepw<<<dim3(4, 128), 224>>>(x, w_max, w_med);
    k_sort<<<128, 224>>>(out);
    k_gather<<<dim3(32, 128), 256>>>(x);
    k_gemm<<<dim3(4, 16, 2), 256, SMEM_GEMM>>>();
    k_final<<<128, 128>>>(out, gmax, bmax, mmax, vmax,
                          gmed, bmed, mmed, vmed);
}